// round 16
// baseline (speedup 1.0000x reference)
#include <cuda_runtime.h>
#include <math.h>

#define BSZ   8
#define NA    256
#define BN    (BSZ*NA)     // 2048
#define LN    12
#define DI    27
#define HD    128
#define NACT  8
#define AG    16           // agents per node_kernel block
#define TI    16           // i-rows per graph_kernel block

#define RPAD4 385          // float4 row stride of transposed weight tile
#define LGRID 148          // persistent lane blocks

// smem float offsets for lane_kernel (512-thread, 2-agent layout)
#define OFF_W4   0                       // 32*385 float4 = 49280 floats
#define OFF_FC1  49280                   // 128*27 = 3456
#define OFF_SX   52736                   // 2 * 12*128 = 3072
#define OFF_SLF  55808                   // 2 * 12*28  = 672
#define OFF_SRED 56480                   // 2 * 48
#define OFF_SWT  56576                   // 2 * 12
#define OFF_SNZ  56600                   // 2 * 8 warp-vote flags
#define SMEM_FLOATS 56616
#define SMEM_BYTES  (SMEM_FLOATS*4)      // 226464 B

__device__ float g_agg[BN*HD];
__device__ float g_hg [BN*HD];
__device__ float g_ai [BN*HD];
__device__ float g_aj [BN*HD];

__device__ __forceinline__ float sigmoidf_(float x){ return 1.0f/(1.0f+expf(-x)); }
typedef unsigned long long u64;
__device__ __forceinline__ void fma2(u64& d, u64 a, u64 b){
    asm("fma.rn.f32x2 %0, %1, %2, %0;" : "+l"(d) : "l"(a), "l"(b));
}
__device__ __forceinline__ float psum(u64 v){
    float lo, hi; asm("mov.b64 {%0, %1}, %2;" : "=f"(lo), "=f"(hi) : "l"(v));
    return lo + hi;
}
// per-group named barrier: 256 threads of agent group (id 1 or 2)
__device__ __forceinline__ void barg(int ag){
    asm volatile("bar.sync %0, 256;" :: "r"(ag + 1) : "memory");
}

// ---------------------------------------------------------------------------
// K1 (persistent): fc1 + GRU + lane attention -> g_agg
// (exact R13/R14 winner: group-local named barriers, 86.5-87us)
// ---------------------------------------------------------------------------
__global__ void __launch_bounds__(512) lane_kernel(
    const float* __restrict__ LF, const float* __restrict__ Hin,
    const float* __restrict__ fc1_w, const float* __restrict__ fc1_b,
    const float* __restrict__ w_ih,  const float* __restrict__ w_hh,
    const float* __restrict__ b_ih,  const float* __restrict__ b_hh,
    const float* __restrict__ lattn_w, const float* __restrict__ lattn_b)
{
    extern __shared__ __align__(16) float smem[];
    float4* sW4  = (float4*)&smem[OFF_W4];
    float*  sFC1 = &smem[OFF_FC1];

    const int t    = threadIdx.x;
    const int lane = t & 31;
    const int ag   = t >> 8;             // agent group 0/1
    const int tt   = t & 255;            // index within group
    const int c    = tt & 127;           // channel / base gate row
    const int lh   = (tt >> 7) & 1;      // lane-half
    const int wig  = (t >> 5) & 7;       // warp index within group

    float* sXg   = &smem[OFF_SX   + ag*1536];
    float* sLFg  = &smem[OFF_SLF  + ag*336];
    float* sREDg = &smem[OFF_SRED + ag*48];
    float* sWTg  = &smem[OFF_SWT  + ag*12];
    float* sNZg  = &smem[OFF_SNZ  + ag*8];

    {
        const float4* wg = (const float4*)w_ih;       // [384][32] float4
        for (int i = t; i < 384*32; i += 512) {
            int row = i >> 5, kp2 = i & 31;
            sW4[kp2*RPAD4 + row] = wg[i];
        }
        for (int i = t; i < HD*DI; i += 512) sFC1[i] = fc1_w[i];
    }
    const float fb  = fc1_b[c];
    const float bir = b_ih[c], biz = b_ih[HD+c], bin_ = b_ih[2*HD+c];
    const float bhr = b_hh[c], bhz = b_hh[HD+c], bhn  = b_hh[2*HD+c];
    const float wl  = lattn_w[DI + c];
    const float wd  = (c < DI) ? lattn_w[c] : 0.0f;
    const float lb  = lattn_b[0];
    const int lfv0 = (tt < LN*DI);
    const int lfv1 = (tt + 256 < LN*DI);
    const int lfo0 = (tt/DI)*28 + (tt%DI);
    const int lfo1 = ((tt+256)/DI)*28 + ((tt+256)%DI);
    __syncthreads();          // block-wide: weight tile visible to both groups

    float pLF0 = 0.f, pLF1 = 0.f, pH[6];
    {
        const int a0 = 2*blockIdx.x + ag;
        const float* lf  = LF  + (size_t)a0*LN*DI;
        if (lfv0) pLF0 = lf[tt];
        if (lfv1) pLF1 = lf[tt+256];
        const float* hin = Hin + (size_t)a0*LN*HD;
        #pragma unroll
        for (int j = 0; j < 6; j++) pH[j] = hin[tt + 256*j];
    }

    for (int base = 2*blockIdx.x; base < BN; base += 2*LGRID) {
        const int a = base + ag;
        barg(ag);   // previous iteration's group readers done

        if (lfv0) sLFg[lfo0] = pLF0;
        if (lfv1) sLFg[lfo1] = pLF1;
        int nzl = 0;
        #pragma unroll
        for (int j = 0; j < 6; j++) nzl |= (pH[j] != 0.0f);
        const int wany = __any_sync(0xffffffffu, nzl);
        if (lane == 0) sNZg[wig] = (float)wany;
        barg(ag);
        const int anynz = (sNZg[0] + sNZg[1] + sNZg[2] + sNZg[3]
                         + sNZg[4] + sNZg[5] + sNZg[6] + sNZg[7]) != 0.0f;

        const int an = base + 2*LGRID + ag;
        if (an < BN) {
            const float* lf  = LF  + (size_t)an*LN*DI;
            if (lfv0) pLF0 = lf[tt];
            if (lfv1) pLF1 = lf[tt+256];
            const float* hin = Hin + (size_t)an*LN*HD;
            #pragma unroll
            for (int j = 0; j < 6; j++) pH[j] = hin[tt + 256*j];
        }

        {
            float acc[6];
            #pragma unroll
            for (int l = 0; l < 6; l++) acc[l] = fb;
            #pragma unroll
            for (int d = 0; d < DI; d++) {
                const float wvd = sFC1[c*DI + d];
                #pragma unroll
                for (int l = 0; l < 6; l++)
                    acc[l] += sLFg[(lh*6 + l)*28 + d]*wvd;
            }
            #pragma unroll
            for (int l = 0; l < 6; l++)
                sXg[(lh*6 + l)*HD + c] = fmaxf(acc[l], 0.0f);
        }
        barg(ag);

        u64 aR[6], aZ[6], aN[6];
        #pragma unroll
        for (int l = 0; l < 6; l++) { aR[l]=0ull; aZ[l]=0ull; aN[l]=0ull; }
        {
            const float4* w0p = sW4 + c;
            const float4* w1p = sW4 + c + 128;
            const float4* w2p = sW4 + c + 256;
            #pragma unroll 2
            for (int kp2 = 0; kp2 < 32; kp2++) {
                const ulonglong2 w0 = *(const ulonglong2*)(w0p + kp2*RPAD4);
                const ulonglong2 w1 = *(const ulonglong2*)(w1p + kp2*RPAD4);
                const ulonglong2 w2 = *(const ulonglong2*)(w2p + kp2*RPAD4);
                #pragma unroll
                for (int l = 0; l < 6; l++) {
                    const ulonglong2 xv = *(const ulonglong2*)&sXg[(lh*6 + l)*HD + kp2*4];
                    fma2(aR[l], xv.x, w0.x); fma2(aR[l], xv.y, w0.y);
                    fma2(aZ[l], xv.x, w1.x); fma2(aZ[l], xv.y, w1.y);
                    fma2(aN[l], xv.x, w2.x); fma2(aN[l], xv.y, w2.y);
                }
            }
        }

        float hnew[6];
        if (!anynz) {
            #pragma unroll
            for (int l = 0; l < 6; l++) {
                const float r = sigmoidf_(psum(aR[l]) + bir + bhr);
                const float z = sigmoidf_(psum(aZ[l]) + biz + bhz);
                const float n = tanhf(psum(aN[l]) + bin_ + r*bhn);
                hnew[l] = (1.0f - z)*n;
            }
        } else {
            const float* hin = Hin + (size_t)a*LN*HD;
            #pragma unroll
            for (int l = 0; l < 6; l++) {
                const int l6 = lh*6 + l;
                float hR = 0.f, hZ = 0.f, hN = 0.f;
                for (int k = 0; k < HD; k++) {
                    const float hv = hin[l6*HD + k];
                    hR += hv * w_hh[(size_t)(c      )*HD + k];
                    hZ += hv * w_hh[(size_t)(c + 128)*HD + k];
                    hN += hv * w_hh[(size_t)(c + 256)*HD + k];
                }
                const float hOld = hin[l6*HD + c];
                const float r = sigmoidf_(psum(aR[l]) + bir + hR + bhr);
                const float z = sigmoidf_(psum(aZ[l]) + biz + hZ + bhz);
                const float n = tanhf(psum(aN[l]) + bin_ + r*(hN + bhn));
                hnew[l] = (1.0f - z)*n + z*hOld;
            }
        }
        barg(ag);            // all gi reads of sXg done (group-local)
        #pragma unroll
        for (int l = 0; l < 6; l++) sXg[(lh*6 + l)*HD + c] = hnew[l];

        #pragma unroll
        for (int l = 0; l < 6; l++) {
            float v = wl*hnew[l];
            if (c < DI) v += wd*sLFg[(lh*6 + l)*28 + c];
            #pragma unroll
            for (int o = 16; o > 0; o >>= 1) v += __shfl_xor_sync(0xffffffffu, v, o);
            if (lane == 0) sREDg[wig*6 + l] = v;
        }
        barg(ag);
        if (tt == 0) {
            float sc[LN]; float m = -3.4e38f;
            #pragma unroll
            for (int l = 0; l < LN; l++) {
                const int wbase = (l < 6) ? 0 : 4;
                const int lr = (l < 6) ? l : l - 6;
                sc[l] = sREDg[(wbase  )*6 + lr] + sREDg[(wbase+1)*6 + lr]
                      + sREDg[(wbase+2)*6 + lr] + sREDg[(wbase+3)*6 + lr] + lb;
                m = fmaxf(m, sc[l]);
            }
            float s = 0.0f;
            #pragma unroll
            for (int l = 0; l < LN; l++) { sc[l] = expf(sc[l]-m); s += sc[l]; }
            const float inv = 1.0f/s;
            #pragma unroll
            for (int l = 0; l < LN; l++) sWTg[l] = sc[l]*inv;
        }
        barg(ag);

        if (lh == 0) {
            float agg = 0.0f;
            #pragma unroll
            for (int l = 0; l < LN; l++) agg += sWTg[l]*sXg[l*HD + c];
            g_agg[(size_t)a*HD + c] = agg;
        }
    }
}

// ---------------------------------------------------------------------------
// K2: hg = gfc(agg); ai/aj = ga1 halves. 16 agents/block, 256 threads.
// (exact R14 winner)
// ---------------------------------------------------------------------------
__global__ void __launch_bounds__(256) node_kernel(
    const float* __restrict__ gfc_w, const float* __restrict__ gfc_b,
    const float* __restrict__ ga1_w, const float* __restrict__ ga1_b)
{
    const int bn0 = blockIdx.x*AG, t = threadIdx.x;
    const int c = t & 127, rh = t >> 7;
    __shared__ __align__(16) float sa[AG][HD];
    __shared__ __align__(16) float sg[AG][HD];

    for (int idx = t; idx < AG*HD; idx += 256) sa[idx>>7][idx&127] = g_agg[(size_t)bn0*HD + idx];
    __syncthreads();

    {
        const float4* gw = (const float4*)(gfc_w + (size_t)c*HD);
        float acc[8];
        #pragma unroll
        for (int a = 0; a < 8; a++) acc[a] = 0.0f;
        #pragma unroll 4
        for (int k4 = 0; k4 < HD/4; k4++) {
            const float4 w = gw[k4];
            #pragma unroll
            for (int a = 0; a < 8; a++) {
                const float4 v = ((const float4*)sa[rh*8 + a])[k4];
                acc[a] += v.x*w.x + v.y*w.y + v.z*w.z + v.w*w.w;
            }
        }
        const float gb = gfc_b[c];
        #pragma unroll
        for (int a = 0; a < 8; a++) {
            const float h = acc[a] + gb;
            sg[rh*8 + a][c] = h;
            g_hg[(size_t)(bn0 + rh*8 + a)*HD + c] = h;
        }
    }
    __syncthreads();

    {
        const float4* wa = (const float4*)(ga1_w + (size_t)c*2*HD);
        const float4* wb = (const float4*)(ga1_w + (size_t)c*2*HD + HD);
        float accA[8], accB[8];
        #pragma unroll
        for (int a = 0; a < 8; a++) { accA[a]=0.f; accB[a]=0.f; }
        #pragma unroll 2
        for (int k4 = 0; k4 < HD/4; k4++) {
            const float4 w1 = wa[k4], w2 = wb[k4];
            #pragma unroll
            for (int a = 0; a < 8; a++) {
                const float4 v = ((const float4*)sg[rh*8 + a])[k4];
                accA[a] += v.x*w1.x + v.y*w1.y + v.z*w1.z + v.w*w1.w;
                accB[a] += v.x*w2.x + v.y*w2.y + v.z*w2.z + v.w*w2.w;
            }
        }
        const float ab = ga1_b[c];
        #pragma unroll
        for (int a = 0; a < 8; a++) {
            g_ai[(size_t)(bn0 + rh*8 + a)*HD + c] = accA[a] + ab;
            g_aj[(size_t)(bn0 + rh*8 + a)*HD + c] = accB[a];
        }
    }
}

// ---------------------------------------------------------------------------
// K3: graph attention + head.  16 i-rows per block, 256 threads (8 warps).
// Change vs R14: h' phase stages hg TRANSPOSED (stride 36, 16B-aligned rows,
// conflict-free LDS.128) -> inner loop fully float4: 72 LDS.128 vs 288 LDS.32.
// ---------------------------------------------------------------------------
__global__ void __launch_bounds__(256) graph_kernel(
    const float* __restrict__ adj,   const float* __restrict__ ga2_w,
    const float* __restrict__ ga2_b, const float* __restrict__ gout_w,
    const float* __restrict__ gout_b,const float* __restrict__ fc2_w,
    const float* __restrict__ fc2_b, float* __restrict__ out)
{
    const int b  = blockIdx.x >> 4;
    const int i0 = (blockIdx.x & 15)*TI;
    const int t = threadIdx.x, lane = t & 31, warp = t >> 5;
    const int c = t & 127, rh = t >> 7;

    __shared__ __align__(16) float sAI[TI*HD];     // ai tile, later h' tile
    __shared__ __align__(16) float sBUF[4608];     // aj stage (132) / hgT stage (36) / agg+fc2w
    __shared__ __align__(16) float sE[TI*NA];      // e / probs, later comm
    __shared__ __align__(16) float sG2[HD];

    for (int idx = t; idx < TI*HD; idx += 256)
        sAI[idx] = g_ai[((size_t)(b*NA + i0))*HD + idx];
    if (t < HD) sG2[t] = ga2_w[t];
    __syncthreads();

    const float g2b = ga2_b[0];
    for (int jc = 0; jc < NA; jc += 32) {
        for (int idx = t; idx < 32*HD; idx += 256) {
            int r = idx >> 7, cc = idx & 127;
            sBUF[r*132 + cc] = g_aj[((size_t)(b*NA + jc))*HD + idx];
        }
        __syncthreads();
        float e0 = 0.f, e1 = 0.f;
        const float4* aj4  = (const float4*)&sBUF[lane*132];
        const float4* ai04 = (const float4*)&sAI[(warp    )*HD];
        const float4* ai14 = (const float4*)&sAI[(warp + 8)*HD];
        const float4* g24  = (const float4*)sG2;
        #pragma unroll 4
        for (int h4 = 0; h4 < HD/4; h4++) {
            const float4 a4 = aj4[h4];
            const float4 i0v = ai04[h4];
            const float4 i1v = ai14[h4];
            const float4 g4 = g24[h4];
            e0 += fmaxf(i0v.x + a4.x, 0.f)*g4.x + fmaxf(i0v.y + a4.y, 0.f)*g4.y
                + fmaxf(i0v.z + a4.z, 0.f)*g4.z + fmaxf(i0v.w + a4.w, 0.f)*g4.w;
            e1 += fmaxf(i1v.x + a4.x, 0.f)*g4.x + fmaxf(i1v.y + a4.y, 0.f)*g4.y
                + fmaxf(i1v.z + a4.z, 0.f)*g4.z + fmaxf(i1v.w + a4.w, 0.f)*g4.w;
        }
        sE[(warp    )*NA + jc + lane] = e0 + g2b;
        sE[(warp + 8)*NA + jc + lane] = e1 + g2b;
        __syncthreads();
    }

    #pragma unroll
    for (int r = 0; r < 2; r++) {
        const int i = warp + 8*r;
        const float* adjr = adj + (size_t)(i0 + i)*NA;
        float pv[8]; float m = -3.4e38f;
        #pragma unroll
        for (int q = 0; q < 8; q++) {
            int j = lane + 32*q;
            float e = sE[i*NA + j];
            if (adjr[j] == 0.0f) e = -1e9f;
            pv[q] = e; m = fmaxf(m, e);
        }
        #pragma unroll
        for (int o = 16; o > 0; o >>= 1) m = fmaxf(m, __shfl_xor_sync(0xffffffffu, m, o));
        float s = 0.0f;
        #pragma unroll
        for (int q = 0; q < 8; q++) { pv[q] = __expf(pv[q]-m); s += pv[q]; }
        #pragma unroll
        for (int o = 16; o > 0; o >>= 1) s += __shfl_xor_sync(0xffffffffu, s, o);
        const float inv = 1.0f/s;
        #pragma unroll
        for (int q = 0; q < 8; q++) sE[i*NA + lane + 32*q] = pv[q]*inv;
    }
    __syncthreads();

    // ---- h' = P @ hg : transposed staging, fully vectorized ----
    float hp[8];
    #pragma unroll
    for (int r = 0; r < 8; r++) hp[r] = 0.0f;
    for (int jc = 0; jc < NA; jc += 32) {
        for (int idx = t; idx < 32*HD; idx += 256) {
            int r = idx >> 7, cc = idx & 127;
            sBUF[cc*36 + r] = g_hg[((size_t)(b*NA + jc))*HD + idx];   // transposed
        }
        __syncthreads();
        const float4* hv4p = (const float4*)&sBUF[c*36];
        #pragma unroll
        for (int j4 = 0; j4 < 8; j4++) {
            const float4 hv = hv4p[j4];
            #pragma unroll
            for (int r = 0; r < 8; r++) {
                const float4 p = *(const float4*)&sE[(rh*8 + r)*NA + jc + j4*4];
                hp[r] += p.x*hv.x + p.y*hv.y + p.z*hv.z + p.w*hv.w;
            }
        }
        __syncthreads();
    }
    #pragma unroll
    for (int r = 0; r < 8; r++) sAI[(rh*8 + r)*HD + c] = hp[r];
    __syncthreads();

    {
        const float4* gw = (const float4*)(gout_w + (size_t)c*HD);
        float acc[8];
        #pragma unroll
        for (int r = 0; r < 8; r++) acc[r] = 0.0f;
        #pragma unroll 2
        for (int k4 = 0; k4 < HD/4; k4++) {
            const float4 w = gw[k4];
            #pragma unroll
            for (int r = 0; r < 8; r++) {
                const float4 v = ((const float4*)&sAI[(rh*8 + r)*HD])[k4];
                acc[r] += v.x*w.x + v.y*w.y + v.z*w.z + v.w*w.w;
            }
        }
        const float gb = gout_b[c];
        #pragma unroll
        for (int r = 0; r < 8; r++) sE[(rh*8 + r)*132 + c] = acc[r] + gb;
    }
    for (int idx = t; idx < TI*HD; idx += 256) {
        int a = idx >> 7, k = idx & 127;
        sBUF[a*132 + k] = g_agg[((size_t)(b*NA + i0))*HD + idx];
    }
    for (int idx = t; idx < NACT*2*HD; idx += 256) {
        int act = idx >> 8, k = idx & 255;
        sBUF[TI*132 + act*257 + k] = fc2_w[idx];
    }
    __syncthreads();

    if (t < 128) {
        const int a = t >> 3, act = t & 7;
        float acc = fc2_b[act];
        const float* sagg = &sBUF[a*132];
        const float* sw1  = &sBUF[TI*132 + act*257];
        const float* scm  = &sE[a*132];
        #pragma unroll 4
        for (int k = 0; k < HD; k++) acc += sagg[k]*sw1[k];
        #pragma unroll 4
        for (int k = 0; k < HD; k++) acc += scm[k]*sw1[HD + k];
        out[((size_t)(b*NA + i0 + a))*NACT + act] = acc;
    }
}

// ---------------------------------------------------------------------------
extern "C" void kernel_launch(void* const* d_in, const int* in_sizes, int n_in,
                              void* d_out, int out_size)
{
    const float* LF      = (const float*)d_in[0];
    const float* Hin     = (const float*)d_in[1];
    const float* adj     = (const float*)d_in[2];
    const float* fc1_w   = (const float*)d_in[3];
    const float* fc1_b   = (const float*)d_in[4];
    const float* w_ih    = (const float*)d_in[5];
    const float* w_hh    = (const float*)d_in[6];
    const float* b_ih    = (const float*)d_in[7];
    const float* b_hh    = (const float*)d_in[8];
    const float* lattn_w = (const float*)d_in[9];
    const float* lattn_b = (const float*)d_in[10];
    const float* gfc_w   = (const float*)d_in[11];
    const float* gfc_b   = (const float*)d_in[12];
    const float* ga1_w   = (const float*)d_in[13];
    const float* ga1_b   = (const float*)d_in[14];
    const float* ga2_w   = (const float*)d_in[15];
    const float* ga2_b   = (const float*)d_in[16];
    const float* gout_w  = (const float*)d_in[17];
    const float* gout_b  = (const float*)d_in[18];
    const float* fc2_w   = (const float*)d_in[19];
    const float* fc2_b   = (const float*)d_in[20];
    float* out = (float*)d_out;

    static int smem_set = 0;
    if (!smem_set) {
        cudaFuncSetAttribute(lane_kernel, cudaFuncAttributeMaxDynamicSharedMemorySize, SMEM_BYTES);
        smem_set = 1;
    }

    lane_kernel<<<LGRID, 512, SMEM_BYTES>>>(LF, Hin, fc1_w, fc1_b, w_ih, w_hh,
                                            b_ih, b_hh, lattn_w, lattn_b);
    node_kernel<<<BN/AG, 256>>>(gfc_w, gfc_b, ga1_w, ga1_b);
    graph_kernel<<<BSZ*(NA/TI), 256>>>(adj, ga2_w, ga2_b, gout_w, gout_b,
                                       fc2_w, fc2_b, out);
}

// round 17
// speedup vs baseline: 1.0931x; 1.0931x over previous
#include <cuda_runtime.h>
#include <math.h>

#define BSZ   8
#define NA    256
#define BN    (BSZ*NA)     // 2048
#define LN    12
#define DI    27
#define HD    128
#define NACT  8
#define AG    16           // agents per node_kernel block
#define TI    16           // i-rows per graph_kernel block

#define RPAD4 385          // float4 row stride of transposed weight tile
#define LGRID 148          // persistent lane blocks

// smem float offsets for lane_kernel (512-thread, 2-agent layout)
#define OFF_W4   0                       // 32*385 float4 = 49280 floats
#define OFF_FC1  49280                   // 128*27 = 3456
#define OFF_SX   52736                   // 2 * 12*128 = 3072
#define OFF_SLF  55808                   // 2 * 12*28  = 672
#define OFF_SRED 56480                   // 2 * 48
#define OFF_SWT  56576                   // 2 * 12
#define OFF_SNZ  56600                   // 2 * 8 warp-vote flags
#define SMEM_FLOATS 56616
#define SMEM_BYTES  (SMEM_FLOATS*4)      // 226464 B

__device__ float g_agg[BN*HD];
__device__ float g_hg [BN*HD];
__device__ float g_ai [BN*HD];
__device__ float g_aj [BN*HD];

__device__ __forceinline__ float sigmoidf_(float x){ return 1.0f/(1.0f+expf(-x)); }
typedef unsigned long long u64;
__device__ __forceinline__ void fma2(u64& d, u64 a, u64 b){
    asm("fma.rn.f32x2 %0, %1, %2, %0;" : "+l"(d) : "l"(a), "l"(b));
}
__device__ __forceinline__ float psum(u64 v){
    float lo, hi; asm("mov.b64 {%0, %1}, %2;" : "=f"(lo), "=f"(hi) : "l"(v));
    return lo + hi;
}
// per-group named barrier: 256 threads of agent group (id 1 or 2)
__device__ __forceinline__ void barg(int ag){
    asm volatile("bar.sync %0, 256;" :: "r"(ag + 1) : "memory");
}

// ---------------------------------------------------------------------------
// K1 (persistent): fc1 + GRU + lane attention -> g_agg
// (exact R13/R14 winner: group-local named barriers, ~87us)
// ---------------------------------------------------------------------------
__global__ void __launch_bounds__(512) lane_kernel(
    const float* __restrict__ LF, const float* __restrict__ Hin,
    const float* __restrict__ fc1_w, const float* __restrict__ fc1_b,
    const float* __restrict__ w_ih,  const float* __restrict__ w_hh,
    const float* __restrict__ b_ih,  const float* __restrict__ b_hh,
    const float* __restrict__ lattn_w, const float* __restrict__ lattn_b)
{
    extern __shared__ __align__(16) float smem[];
    float4* sW4  = (float4*)&smem[OFF_W4];
    float*  sFC1 = &smem[OFF_FC1];

    const int t    = threadIdx.x;
    const int lane = t & 31;
    const int ag   = t >> 8;             // agent group 0/1
    const int tt   = t & 255;            // index within group
    const int c    = tt & 127;           // channel / base gate row
    const int lh   = (tt >> 7) & 1;      // lane-half
    const int wig  = (t >> 5) & 7;       // warp index within group

    float* sXg   = &smem[OFF_SX   + ag*1536];
    float* sLFg  = &smem[OFF_SLF  + ag*336];
    float* sREDg = &smem[OFF_SRED + ag*48];
    float* sWTg  = &smem[OFF_SWT  + ag*12];
    float* sNZg  = &smem[OFF_SNZ  + ag*8];

    {
        const float4* wg = (const float4*)w_ih;       // [384][32] float4
        for (int i = t; i < 384*32; i += 512) {
            int row = i >> 5, kp2 = i & 31;
            sW4[kp2*RPAD4 + row] = wg[i];
        }
        for (int i = t; i < HD*DI; i += 512) sFC1[i] = fc1_w[i];
    }
    const float fb  = fc1_b[c];
    const float bir = b_ih[c], biz = b_ih[HD+c], bin_ = b_ih[2*HD+c];
    const float bhr = b_hh[c], bhz = b_hh[HD+c], bhn  = b_hh[2*HD+c];
    const float wl  = lattn_w[DI + c];
    const float wd  = (c < DI) ? lattn_w[c] : 0.0f;
    const float lb  = lattn_b[0];
    const int lfv0 = (tt < LN*DI);
    const int lfv1 = (tt + 256 < LN*DI);
    const int lfo0 = (tt/DI)*28 + (tt%DI);
    const int lfo1 = ((tt+256)/DI)*28 + ((tt+256)%DI);
    __syncthreads();          // block-wide: weight tile visible to both groups

    float pLF0 = 0.f, pLF1 = 0.f, pH[6];
    {
        const int a0 = 2*blockIdx.x + ag;
        const float* lf  = LF  + (size_t)a0*LN*DI;
        if (lfv0) pLF0 = lf[tt];
        if (lfv1) pLF1 = lf[tt+256];
        const float* hin = Hin + (size_t)a0*LN*HD;
        #pragma unroll
        for (int j = 0; j < 6; j++) pH[j] = hin[tt + 256*j];
    }

    for (int base = 2*blockIdx.x; base < BN; base += 2*LGRID) {
        const int a = base + ag;
        barg(ag);   // previous iteration's group readers done

        if (lfv0) sLFg[lfo0] = pLF0;
        if (lfv1) sLFg[lfo1] = pLF1;
        int nzl = 0;
        #pragma unroll
        for (int j = 0; j < 6; j++) nzl |= (pH[j] != 0.0f);
        const int wany = __any_sync(0xffffffffu, nzl);
        if (lane == 0) sNZg[wig] = (float)wany;
        barg(ag);
        const int anynz = (sNZg[0] + sNZg[1] + sNZg[2] + sNZg[3]
                         + sNZg[4] + sNZg[5] + sNZg[6] + sNZg[7]) != 0.0f;

        const int an = base + 2*LGRID + ag;
        if (an < BN) {
            const float* lf  = LF  + (size_t)an*LN*DI;
            if (lfv0) pLF0 = lf[tt];
            if (lfv1) pLF1 = lf[tt+256];
            const float* hin = Hin + (size_t)an*LN*HD;
            #pragma unroll
            for (int j = 0; j < 6; j++) pH[j] = hin[tt + 256*j];
        }

        {
            float acc[6];
            #pragma unroll
            for (int l = 0; l < 6; l++) acc[l] = fb;
            #pragma unroll
            for (int d = 0; d < DI; d++) {
                const float wvd = sFC1[c*DI + d];
                #pragma unroll
                for (int l = 0; l < 6; l++)
                    acc[l] += sLFg[(lh*6 + l)*28 + d]*wvd;
            }
            #pragma unroll
            for (int l = 0; l < 6; l++)
                sXg[(lh*6 + l)*HD + c] = fmaxf(acc[l], 0.0f);
        }
        barg(ag);

        u64 aR[6], aZ[6], aN[6];
        #pragma unroll
        for (int l = 0; l < 6; l++) { aR[l]=0ull; aZ[l]=0ull; aN[l]=0ull; }
        {
            const float4* w0p = sW4 + c;
            const float4* w1p = sW4 + c + 128;
            const float4* w2p = sW4 + c + 256;
            #pragma unroll 2
            for (int kp2 = 0; kp2 < 32; kp2++) {
                const ulonglong2 w0 = *(const ulonglong2*)(w0p + kp2*RPAD4);
                const ulonglong2 w1 = *(const ulonglong2*)(w1p + kp2*RPAD4);
                const ulonglong2 w2 = *(const ulonglong2*)(w2p + kp2*RPAD4);
                #pragma unroll
                for (int l = 0; l < 6; l++) {
                    const ulonglong2 xv = *(const ulonglong2*)&sXg[(lh*6 + l)*HD + kp2*4];
                    fma2(aR[l], xv.x, w0.x); fma2(aR[l], xv.y, w0.y);
                    fma2(aZ[l], xv.x, w1.x); fma2(aZ[l], xv.y, w1.y);
                    fma2(aN[l], xv.x, w2.x); fma2(aN[l], xv.y, w2.y);
                }
            }
        }

        float hnew[6];
        if (!anynz) {
            #pragma unroll
            for (int l = 0; l < 6; l++) {
                const float r = sigmoidf_(psum(aR[l]) + bir + bhr);
                const float z = sigmoidf_(psum(aZ[l]) + biz + bhz);
                const float n = tanhf(psum(aN[l]) + bin_ + r*bhn);
                hnew[l] = (1.0f - z)*n;
            }
        } else {
            const float* hin = Hin + (size_t)a*LN*HD;
            #pragma unroll
            for (int l = 0; l < 6; l++) {
                const int l6 = lh*6 + l;
                float hR = 0.f, hZ = 0.f, hN = 0.f;
                for (int k = 0; k < HD; k++) {
                    const float hv = hin[l6*HD + k];
                    hR += hv * w_hh[(size_t)(c      )*HD + k];
                    hZ += hv * w_hh[(size_t)(c + 128)*HD + k];
                    hN += hv * w_hh[(size_t)(c + 256)*HD + k];
                }
                const float hOld = hin[l6*HD + c];
                const float r = sigmoidf_(psum(aR[l]) + bir + hR + bhr);
                const float z = sigmoidf_(psum(aZ[l]) + biz + hZ + bhz);
                const float n = tanhf(psum(aN[l]) + bin_ + r*(hN + bhn));
                hnew[l] = (1.0f - z)*n + z*hOld;
            }
        }
        barg(ag);            // all gi reads of sXg done (group-local)
        #pragma unroll
        for (int l = 0; l < 6; l++) sXg[(lh*6 + l)*HD + c] = hnew[l];

        #pragma unroll
        for (int l = 0; l < 6; l++) {
            float v = wl*hnew[l];
            if (c < DI) v += wd*sLFg[(lh*6 + l)*28 + c];
            #pragma unroll
            for (int o = 16; o > 0; o >>= 1) v += __shfl_xor_sync(0xffffffffu, v, o);
            if (lane == 0) sREDg[wig*6 + l] = v;
        }
        barg(ag);
        if (tt == 0) {
            float sc[LN]; float m = -3.4e38f;
            #pragma unroll
            for (int l = 0; l < LN; l++) {
                const int wbase = (l < 6) ? 0 : 4;
                const int lr = (l < 6) ? l : l - 6;
                sc[l] = sREDg[(wbase  )*6 + lr] + sREDg[(wbase+1)*6 + lr]
                      + sREDg[(wbase+2)*6 + lr] + sREDg[(wbase+3)*6 + lr] + lb;
                m = fmaxf(m, sc[l]);
            }
            float s = 0.0f;
            #pragma unroll
            for (int l = 0; l < LN; l++) { sc[l] = expf(sc[l]-m); s += sc[l]; }
            const float inv = 1.0f/s;
            #pragma unroll
            for (int l = 0; l < LN; l++) sWTg[l] = sc[l]*inv;
        }
        barg(ag);

        if (lh == 0) {
            float agg = 0.0f;
            #pragma unroll
            for (int l = 0; l < LN; l++) agg += sWTg[l]*sXg[l*HD + c];
            g_agg[(size_t)a*HD + c] = agg;
        }
    }
}

// ---------------------------------------------------------------------------
// K2: hg = gfc(agg); ai/aj = ga1 halves. 16 agents/block, 256 threads.
// Change vs R14: float4 staging load of the agg tile.
// ---------------------------------------------------------------------------
__global__ void __launch_bounds__(256) node_kernel(
    const float* __restrict__ gfc_w, const float* __restrict__ gfc_b,
    const float* __restrict__ ga1_w, const float* __restrict__ ga1_b)
{
    const int bn0 = blockIdx.x*AG, t = threadIdx.x;
    const int c = t & 127, rh = t >> 7;
    __shared__ __align__(16) float sa[AG][HD];
    __shared__ __align__(16) float sg[AG][HD];

    {
        const float4* src4 = (const float4*)(g_agg + (size_t)bn0*HD);
        float4* dst4 = (float4*)sa;
        for (int i4 = t; i4 < AG*HD/4; i4 += 256) dst4[i4] = src4[i4];
    }
    __syncthreads();

    {
        const float4* gw = (const float4*)(gfc_w + (size_t)c*HD);
        float acc[8];
        #pragma unroll
        for (int a = 0; a < 8; a++) acc[a] = 0.0f;
        #pragma unroll 4
        for (int k4 = 0; k4 < HD/4; k4++) {
            const float4 w = gw[k4];
            #pragma unroll
            for (int a = 0; a < 8; a++) {
                const float4 v = ((const float4*)sa[rh*8 + a])[k4];
                acc[a] += v.x*w.x + v.y*w.y + v.z*w.z + v.w*w.w;
            }
        }
        const float gb = gfc_b[c];
        #pragma unroll
        for (int a = 0; a < 8; a++) {
            const float h = acc[a] + gb;
            sg[rh*8 + a][c] = h;
            g_hg[(size_t)(bn0 + rh*8 + a)*HD + c] = h;
        }
    }
    __syncthreads();

    {
        const float4* wa = (const float4*)(ga1_w + (size_t)c*2*HD);
        const float4* wb = (const float4*)(ga1_w + (size_t)c*2*HD + HD);
        float accA[8], accB[8];
        #pragma unroll
        for (int a = 0; a < 8; a++) { accA[a]=0.f; accB[a]=0.f; }
        #pragma unroll 2
        for (int k4 = 0; k4 < HD/4; k4++) {
            const float4 w1 = wa[k4], w2 = wb[k4];
            #pragma unroll
            for (int a = 0; a < 8; a++) {
                const float4 v = ((const float4*)sg[rh*8 + a])[k4];
                accA[a] += v.x*w1.x + v.y*w1.y + v.z*w1.z + v.w*w1.w;
                accB[a] += v.x*w2.x + v.y*w2.y + v.z*w2.z + v.w*w2.w;
            }
        }
        const float ab = ga1_b[c];
        #pragma unroll
        for (int a = 0; a < 8; a++) {
            g_ai[(size_t)(bn0 + rh*8 + a)*HD + c] = accA[a] + ab;
            g_aj[(size_t)(bn0 + rh*8 + a)*HD + c] = accB[a];
        }
    }
}

// ---------------------------------------------------------------------------
// K3: graph attention + head.  16 i-rows per block, 256 threads (8 warps).
// Changes vs R14 winner: ALL gmem->smem stages vectorized to float4
// (aj/hg chunks: 4x LDG.128 per thread vs 16x LDG.32; conflict-free STS.128).
// h' inner loop = R14 scalar form (132-stride).
// ---------------------------------------------------------------------------
__global__ void __launch_bounds__(256) graph_kernel(
    const float* __restrict__ adj,   const float* __restrict__ ga2_w,
    const float* __restrict__ ga2_b, const float* __restrict__ gout_w,
    const float* __restrict__ gout_b,const float* __restrict__ fc2_w,
    const float* __restrict__ fc2_b, float* __restrict__ out)
{
    const int b  = blockIdx.x >> 4;
    const int i0 = (blockIdx.x & 15)*TI;
    const int t = threadIdx.x, lane = t & 31, warp = t >> 5;
    const int c = t & 127, rh = t >> 7;

    __shared__ __align__(16) float sAI[TI*HD];     // ai tile, later h' tile
    __shared__ __align__(16) float sBUF[4608];     // aj/hg stage (132-stride), later agg+fc2w
    __shared__ __align__(16) float sE[TI*NA];      // e / probs, later comm
    __shared__ __align__(16) float sG2[HD];

    {
        const float4* src4 = (const float4*)(g_ai + (size_t)(b*NA + i0)*HD);
        float4* dst4 = (float4*)sAI;
        for (int i4 = t; i4 < TI*HD/4; i4 += 256) dst4[i4] = src4[i4];
    }
    if (t < HD) sG2[t] = ga2_w[t];
    __syncthreads();

    const float g2b = ga2_b[0];
    for (int jc = 0; jc < NA; jc += 32) {
        {   // float4 stage: r = i4>>5, cc4 = i4&31 -> sBUF4[r*33 + cc4]
            const float4* src4 = (const float4*)(g_aj + (size_t)(b*NA + jc)*HD);
            float4* dst4 = (float4*)sBUF;
            #pragma unroll
            for (int k = 0; k < 4; k++) {
                const int i4 = t + k*256;
                dst4[(i4 >> 5)*33 + (i4 & 31)] = src4[i4];
            }
        }
        __syncthreads();
        float e0 = 0.f, e1 = 0.f;
        const float4* aj4  = (const float4*)&sBUF[lane*132];
        const float4* ai04 = (const float4*)&sAI[(warp    )*HD];
        const float4* ai14 = (const float4*)&sAI[(warp + 8)*HD];
        const float4* g24  = (const float4*)sG2;
        #pragma unroll 4
        for (int h4 = 0; h4 < HD/4; h4++) {
            const float4 a4 = aj4[h4];
            const float4 i0v = ai04[h4];
            const float4 i1v = ai14[h4];
            const float4 g4 = g24[h4];
            e0 += fmaxf(i0v.x + a4.x, 0.f)*g4.x + fmaxf(i0v.y + a4.y, 0.f)*g4.y
                + fmaxf(i0v.z + a4.z, 0.f)*g4.z + fmaxf(i0v.w + a4.w, 0.f)*g4.w;
            e1 += fmaxf(i1v.x + a4.x, 0.f)*g4.x + fmaxf(i1v.y + a4.y, 0.f)*g4.y
                + fmaxf(i1v.z + a4.z, 0.f)*g4.z + fmaxf(i1v.w + a4.w, 0.f)*g4.w;
        }
        sE[(warp    )*NA + jc + lane] = e0 + g2b;
        sE[(warp + 8)*NA + jc + lane] = e1 + g2b;
        __syncthreads();
    }

    #pragma unroll
    for (int r = 0; r < 2; r++) {
        const int i = warp + 8*r;
        const float* adjr = adj + (size_t)(i0 + i)*NA;
        float pv[8]; float m = -3.4e38f;
        #pragma unroll
        for (int q = 0; q < 8; q++) {
            int j = lane + 32*q;
            float e = sE[i*NA + j];
            if (adjr[j] == 0.0f) e = -1e9f;
            pv[q] = e; m = fmaxf(m, e);
        }
        #pragma unroll
        for (int o = 16; o > 0; o >>= 1) m = fmaxf(m, __shfl_xor_sync(0xffffffffu, m, o));
        float s = 0.0f;
        #pragma unroll
        for (int q = 0; q < 8; q++) { pv[q] = __expf(pv[q]-m); s += pv[q]; }
        #pragma unroll
        for (int o = 16; o > 0; o >>= 1) s += __shfl_xor_sync(0xffffffffu, s, o);
        const float inv = 1.0f/s;
        #pragma unroll
        for (int q = 0; q < 8; q++) sE[i*NA + lane + 32*q] = pv[q]*inv;
    }
    __syncthreads();

    // ---- h' = P @ hg (R14 form; float4 staging) ----
    float hp[8];
    #pragma unroll
    for (int r = 0; r < 8; r++) hp[r] = 0.0f;
    for (int jc = 0; jc < NA; jc += 32) {
        {
            const float4* src4 = (const float4*)(g_hg + (size_t)(b*NA + jc)*HD);
            float4* dst4 = (float4*)sBUF;
            #pragma unroll
            for (int k = 0; k < 4; k++) {
                const int i4 = t + k*256;
                dst4[(i4 >> 5)*33 + (i4 & 31)] = src4[i4];
            }
        }
        __syncthreads();
        for (int jr = 0; jr < 32; jr++) {
            const float hv = sBUF[jr*132 + c];
            #pragma unroll
            for (int r = 0; r < 8; r++) hp[r] += sE[(rh*8 + r)*NA + jc + jr]*hv;
        }
        __syncthreads();
    }
    #pragma unroll
    for (int r = 0; r < 8; r++) sAI[(rh*8 + r)*HD + c] = hp[r];
    __syncthreads();

    {
        const float4* gw = (const float4*)(gout_w + (size_t)c*HD);
        float acc[8];
        #pragma unroll
        for (int r = 0; r < 8; r++) acc[r] = 0.0f;
        #pragma unroll 2
        for (int k4 = 0; k4 < HD/4; k4++) {
            const float4 w = gw[k4];
            #pragma unroll
            for (int r = 0; r < 8; r++) {
                const float4 v = ((const float4*)&sAI[(rh*8 + r)*HD])[k4];
                acc[r] += v.x*w.x + v.y*w.y + v.z*w.z + v.w*w.w;
            }
        }
        const float gb = gout_b[c];
        #pragma unroll
        for (int r = 0; r < 8; r++) sE[(rh*8 + r)*132 + c] = acc[r] + gb;
    }
    {   // agg tile stage (float4, stride 132 -> 33 float4s)
        const float4* src4 = (const float4*)(g_agg + (size_t)(b*NA + i0)*HD);
        float4* dst4 = (float4*)sBUF;
        #pragma unroll
        for (int k = 0; k < 2; k++) {
            const int i4 = t + k*256;
            dst4[(i4 >> 5)*33 + (i4 & 31)] = src4[i4];
        }
    }
    for (int idx = t; idx < NACT*2*HD; idx += 256) {
        int act = idx >> 8, k = idx & 255;
        sBUF[TI*132 + act*257 + k] = fc2_w[idx];
    }
    __syncthreads();

    if (t < 128) {
        const int a = t >> 3, act = t & 7;
        float acc = fc2_b[act];
        const float* sagg = &sBUF[a*132];
        const float* sw1  = &sBUF[TI*132 + act*257];
        const float* scm  = &sE[a*132];
        #pragma unroll 4
        for (int k = 0; k < HD; k++) acc += sagg[k]*sw1[k];
        #pragma unroll 4
        for (int k = 0; k < HD; k++) acc += scm[k]*sw1[HD + k];
        out[((size_t)(b*NA + i0 + a))*NACT + act] = acc;
    }
}

// ---------------------------------------------------------------------------
extern "C" void kernel_launch(void* const* d_in, const int* in_sizes, int n_in,
                              void* d_out, int out_size)
{
    const float* LF      = (const float*)d_in[0];
    const float* Hin     = (const float*)d_in[1];
    const float* adj     = (const float*)d_in[2];
    const float* fc1_w   = (const float*)d_in[3];
    const float* fc1_b   = (const float*)d_in[4];
    const float* w_ih    = (const float*)d_in[5];
    const float* w_hh    = (const float*)d_in[6];
    const float* b_ih    = (const float*)d_in[7];
    const float* b_hh    = (const float*)d_in[8];
    const float* lattn_w = (const float*)d_in[9];
    const float* lattn_b = (const float*)d_in[10];
    const float* gfc_w   = (const float*)d_in[11];
    const float* gfc_b   = (const float*)d_in[12];
    const float* ga1_w   = (const float*)d_in[13];
    const float* ga1_b   = (const float*)d_in[14];
    const float* ga2_w   = (const float*)d_in[15];
    const float* ga2_b   = (const float*)d_in[16];
    const float* gout_w  = (const float*)d_in[17];
    const float* gout_b  = (const float*)d_in[18];
    const float* fc2_w   = (const float*)d_in[19];
    const float* fc2_b   = (const float*)d_in[20];
    float* out = (float*)d_out;

    static int smem_set = 0;
    if (!smem_set) {
        cudaFuncSetAttribute(lane_kernel, cudaFuncAttributeMaxDynamicSharedMemorySize, SMEM_BYTES);
        smem_set = 1;
    }

    lane_kernel<<<LGRID, 512, SMEM_BYTES>>>(LF, Hin, fc1_w, fc1_b, w_ih, w_hh,
                                            b_ih, b_hh, lattn_w, lattn_b);
    node_kernel<<<BN/AG, 256>>>(gfc_w, gfc_b, ga1_w, ga1_b);
    graph_kernel<<<BSZ*(NA/TI), 256>>>(adj, ga2_w, ga2_b, gout_w, gout_b,
                                       fc2_w, fc2_b, out);
}